// round 1
// baseline (speedup 1.0000x reference)
#include <cuda_runtime.h>

// Problem constants (fixed shapes for RotatedGridPool_70970039599822)
constexpr int B = 4;
constexpr int C = 256;
constexpr int H = 200;
constexpr int W = 176;
constexpr int N = 128;
constexpr int G = 7;
constexpr int GG = G * G;          // 49
constexpr float MIN_X = 0.0f;
constexpr float MIN_Y = -40.0f;

__global__ __launch_bounds__(256)
void rotated_grid_pool_kernel(const float* __restrict__ feat,
                              const float* __restrict__ rois,
                              const float* __restrict__ voxel,
                              const int*   __restrict__ fms,
                              float* __restrict__ out) {
    const int roi = blockIdx.x;          // 0 .. B*N-1
    const int b   = roi / N;

    // Per-grid-point precomputed sampling data (49 points x 4 corners)
    __shared__ int   s_off[4][GG];   // offset within a channel plane (clamped)
    __shared__ float s_w[4][GG];     // bilinear weight (0 if corner invalid)

    const int tid = threadIdx.x;

    if (tid < GG) {
        const float* r = rois + roi * 7;
        const float cx  = r[0];
        const float cy  = r[1];
        const float dx  = r[3];
        const float dy  = r[4];
        const float ang = r[6];
        const float stride = (float)fms[0];
        const float vx = voxel[0] * stride;
        const float vy = voxel[1] * stride;

        const float x1 = (cx - dx * 0.5f - MIN_X) / vx;
        const float x2 = (cx + dx * 0.5f - MIN_X) / vx;
        const float y1 = (cy - dy * 0.5f - MIN_Y) / vy;
        const float y2 = (cy + dy * 0.5f - MIN_Y) / vy;

        const float ca = cosf(ang);
        const float sa = sinf(ang);
        const float scale1 = (y2 - y1) / fmaxf(x2 - x1, 0.01f);
        const float scale2 = (x2 - x1) / fmaxf(y2 - y1, 0.01f);

        const float invWm1 = 1.0f / (float)(W - 1);
        const float invHm1 = 1.0f / (float)(H - 1);
        const float t00 = (x2 - x1) * invWm1 * ca;
        const float t01 = (x2 - x1) * invWm1 * (-sa) * scale1;
        const float t02 = (x1 + x2 - (float)W + 1.0f) * invWm1;
        const float t10 = (y2 - y1) * invHm1 * sa * scale2;
        const float t11 = (y2 - y1) * invHm1 * ca;
        const float t12 = (y1 + y2 - (float)H + 1.0f) * invHm1;

        const int gyi = tid / G;
        const int gxi = tid - gyi * G;
        const float xxv = (2.0f * (float)gxi + 1.0f) / (float)G - 1.0f;
        const float yyv = (2.0f * (float)gyi + 1.0f) / (float)G - 1.0f;

        const float gx = t00 * xxv + t01 * yyv + t02;
        const float gy = t10 * xxv + t11 * yyv + t12;

        // grid_sample bilinear, align_corners=False, zeros padding
        const float ix = ((gx + 1.0f) * (float)W - 1.0f) * 0.5f;
        const float iy = ((gy + 1.0f) * (float)H - 1.0f) * 0.5f;

        const float x0f = floorf(ix);
        const float y0f = floorf(iy);
        const float wx1 = ix - x0f, wx0 = 1.0f - wx1;
        const float wy1 = iy - y0f, wy0 = 1.0f - wy1;
        const int x0 = (int)x0f;
        const int y0 = (int)y0f;
        const int x1i = x0 + 1;
        const int y1i = y0 + 1;

        // corner order: (y0,x0) (y0,x1) (y1,x0) (y1,x1)
        const int   cxs[4] = {x0, x1i, x0, x1i};
        const int   cys[4] = {y0, y0,  y1i, y1i};
        const float cws[4] = {wy0 * wx0, wy0 * wx1, wy1 * wx0, wy1 * wx1};

        #pragma unroll
        for (int k = 0; k < 4; k++) {
            const int xi = cxs[k];
            const int yi = cys[k];
            const bool valid = (xi >= 0) && (xi <= W - 1) && (yi >= 0) && (yi <= H - 1);
            const int xc = min(max(xi, 0), W - 1);
            const int yc = min(max(yi, 0), H - 1);
            s_off[k][tid] = yc * W + xc;
            s_w[k][tid]   = valid ? cws[k] : 0.0f;
        }
    }
    __syncthreads();

    const float* fbase = feat + (size_t)b * C * H * W;
    float* o = out + (size_t)roi * C * GG;

    // C*GG = 12544 elements per roi; 256 threads -> 49 iterations each.
    // Output writes are fully contiguous across j.
    for (int j = tid; j < C * GG; j += 256) {
        const int c = j / GG;
        const int g = j - c * GG;
        const float* fp = fbase + c * (H * W);

        float acc;
        acc  = __ldg(fp + s_off[0][g]) * s_w[0][g];
        acc  = fmaf(__ldg(fp + s_off[1][g]), s_w[1][g], acc);
        acc  = fmaf(__ldg(fp + s_off[2][g]), s_w[2][g], acc);
        acc  = fmaf(__ldg(fp + s_off[3][g]), s_w[3][g], acc);
        o[j] = acc;
    }
}

extern "C" void kernel_launch(void* const* d_in, const int* in_sizes, int n_in,
                              void* d_out, int out_size) {
    const float* feat  = (const float*)d_in[0];
    const float* rois  = (const float*)d_in[1];
    const float* voxel = (const float*)d_in[2];
    const int*   fms   = (const int*)d_in[3];
    float* out = (float*)d_out;

    rotated_grid_pool_kernel<<<B * N, 256>>>(feat, rois, voxel, fms, out);
}